// round 15
// baseline (speedup 1.0000x reference)
#include <cuda_runtime.h>
#include <cuda_bf16.h>
#include <cstdint>

// ---------------- problem constants ----------------
constexpr int kD     = 128;
constexpr int kNH    = 8;
constexpr int kHD    = 16;
constexpr int kNW1   = 4096;
constexpr int kL1    = 36;
constexpr int kNW2   = 1024;
constexpr int kL2    = 100;
constexpr int kN1    = (kNW1 / 2) * (kL1 + kL1 / 2);   // 110592
constexpr int kN2    = (kNW2 / 2) * (kL2 + kL2 / 2);   // 76800
constexpr int kNTOK  = kN1 + kN2;                      // 187392 == 1464*128

static_assert(kNTOK % 128 == 0, "M tile");

extern __shared__ char smem_raw[];

// ---------------- device scratch (all inter-stage data pre-split bf16) -----
__device__ __nv_bfloat16 g_QKih[(size_t)kNTOK * 128];
__device__ __nv_bfloat16 g_QKil[(size_t)kNTOK * 128];
__device__ __nv_bfloat16 g_Fh  [(size_t)kNTOK * 128];   // feat, slot order
__device__ __nv_bfloat16 g_Fl  [(size_t)kNTOK * 128];
__device__ __nv_bfloat16 g_QKph[(size_t)kNTOK * 256];
__device__ __nv_bfloat16 g_QKpl[(size_t)kNTOK * 256];
__device__ __nv_bfloat16 g_Vph [(size_t)kNTOK * 128];
__device__ __nv_bfloat16 g_Vpl [(size_t)kNTOK * 128];
__device__ __nv_bfloat16 g_Oh  [(size_t)kNTOK * 128];
__device__ __nv_bfloat16 g_Ol  [(size_t)kNTOK * 128];
__device__ int   g_s2t [kNTOK];
__device__ float g_bias[512];
__device__ __nv_bfloat16 g_Wh[512 * 128];
__device__ __nv_bfloat16 g_Wl[512 * 128];

// ---------------- PTX helpers (sm_80+ generic) ----------------
__device__ __forceinline__ uint32_t smem_u32(const void* p) {
    uint32_t a;
    asm("{ .reg .u64 t; cvta.to.shared.u64 t, %1; cvt.u32.u64 %0, t; }"
        : "=r"(a) : "l"(p));
    return a;
}
__device__ __forceinline__ void cp_async16(uint32_t dst, const void* src) {
    asm volatile("cp.async.cg.shared.global [%0], [%1], 16;"
                 :: "r"(dst), "l"(src) : "memory");
}
__device__ __forceinline__ void cp_async_commit_wait() {
    asm volatile("cp.async.commit_group;" ::: "memory");
    asm volatile("cp.async.wait_group 0;" ::: "memory");
}
__device__ __forceinline__ void ldsm_x4(uint32_t* r, uint32_t a) {
    asm volatile("ldmatrix.sync.aligned.m8n8.x4.shared.b16 {%0,%1,%2,%3}, [%4];"
                 : "=r"(r[0]), "=r"(r[1]), "=r"(r[2]), "=r"(r[3]) : "r"(a));
}
__device__ __forceinline__ void ldsm_x2(uint32_t* r, uint32_t a) {
    asm volatile("ldmatrix.sync.aligned.m8n8.x2.shared.b16 {%0,%1}, [%2];"
                 : "=r"(r[0]), "=r"(r[1]) : "r"(a));
}
__device__ __forceinline__ void ldsm_x2_trans(uint32_t* r, uint32_t a) {
    asm volatile("ldmatrix.sync.aligned.m8n8.x2.trans.shared.b16 {%0,%1}, [%2];"
                 : "=r"(r[0]), "=r"(r[1]) : "r"(a));
}
__device__ __forceinline__ void mma_bf16(float* d, const uint32_t* a, const uint32_t* b) {
    asm volatile(
        "mma.sync.aligned.m16n8k16.row.col.f32.bf16.bf16.f32 "
        "{%0,%1,%2,%3}, {%4,%5,%6,%7}, {%8,%9}, {%0,%1,%2,%3};"
        : "+f"(d[0]), "+f"(d[1]), "+f"(d[2]), "+f"(d[3])
        : "r"(a[0]), "r"(a[1]), "r"(a[2]), "r"(a[3]), "r"(b[0]), "r"(b[1]));
}
__device__ __forceinline__ void pack_split(float x, float y, uint32_t& h, uint32_t& l) {
    __nv_bfloat162 hh = __floats2bfloat162_rn(x, y);
    __nv_bfloat162 ll = __floats2bfloat162_rn(x - __bfloat162float(hh.x),
                                              y - __bfloat162float(hh.y));
    h = *reinterpret_cast<uint32_t*>(&hh);
    l = *reinterpret_cast<uint32_t*>(&ll);
}
__device__ __forceinline__ void split_store(__nv_bfloat16* hi, __nv_bfloat16* lo,
                                            size_t idx, float4 v) {
    uint32_t h0, l0, h1, l1;
    pack_split(v.x, v.y, h0, l0);
    pack_split(v.z, v.w, h1, l1);
    *reinterpret_cast<uint2*>(hi + idx) = make_uint2(h0, h1);
    *reinterpret_cast<uint2*>(lo + idx) = make_uint2(l0, l1);
}

// ---------------- fused prep: gather planes + weight split + maps ---------
constexpr int kNWALL = kNW1 + kNW2;                 // 5120
constexpr int kPrepBlocks = (512 * 128) / 256;      // 256

__global__ __launch_bounds__(256)
void gather_prep_kernel(const float* __restrict__ feat,
                        const float* __restrict__ pos1,
                        const float* __restrict__ pos2,
                        const int* __restrict__ inds1,
                        const int* __restrict__ inds2,
                        const float* __restrict__ Wi,
                        const float* __restrict__ Wo,
                        const float* __restrict__ bi,
                        const float* __restrict__ bo) {
    int w = blockIdx.x;
    if (w >= kNWALL) {
        int t = (w - kNWALL) * 256 + threadIdx.x;
        if (w == kNWALL && threadIdx.x < 256) {
            for (int b = threadIdx.x; b < 512; b += 256) {
                float v = (b < 128) ? bi[b] * 0.25f
                                    : (b < 384 ? bi[b] : bo[b - 384]);
                g_bias[b] = v;
            }
        }
        if (t < 512 * 128) {
            float wv = (t < 384 * 128) ? Wi[t] : Wo[t - 384 * 128];
            if (t < 128 * 128) wv *= 0.25f;   // fold score scale into Q
            __nv_bfloat16 h = __float2bfloat16(wv);
            __nv_bfloat16 l = __float2bfloat16(wv - __bfloat162float(h));
            g_Wh[t] = h;
            g_Wl[t] = l;
        }
        return;
    }
    int Lv, slot0;
    const int* inds;
    const float* pos;
    if (w < kNW1) {
        Lv    = (w & 1) ? (kL1 / 2) : kL1;
        slot0 = (w >> 1) * (kL1 + kL1 / 2) + (w & 1) * kL1;
        inds  = inds1 + w * kL1;
        pos   = pos1 + (size_t)w * kL1 * 128;
    } else {
        int w2 = w - kNW1;
        Lv    = (w2 & 1) ? (kL2 / 2) : kL2;
        slot0 = kN1 + (w2 >> 1) * (kL2 + kL2 / 2) + (w2 & 1) * kL2;
        inds  = inds2 + w2 * kL2;
        pos   = pos2 + (size_t)w2 * kL2 * 128;
    }
    for (int t = threadIdx.x; t < Lv * 32; t += 256) {
        int l = t >> 5, c = t & 31;
        int tok = inds[l];
        float4 f = reinterpret_cast<const float4*>(feat + (size_t)tok * 128)[c];
        float4 p = reinterpret_cast<const float4*>(pos + (size_t)l * 128)[c];
        float4 r;
        r.x = f.x + p.x; r.y = f.y + p.y; r.z = f.z + p.z; r.w = f.w + p.w;
        size_t idx = (size_t)(slot0 + l) * 128 + c * 4;
        split_store(g_QKih, g_QKil, idx, r);
        split_store(g_Fh, g_Fl, idx, f);
        if (c == 0) g_s2t[slot0 + l] = tok;
    }
}

// ---------------- multi-tile HMMA GEMM, B resident, A reg-prefetch --------
constexpr int kLds  = 136;
constexpr int kMT   = 64;
constexpr int kTcSmem = (2 * kMT + 2 * 128) * kLds * 2;   // 104448 B

template <bool OUTF32, int TPB>
__device__ __forceinline__ void gemm_multi(
    const __nv_bfloat16* __restrict__ Ah, const __nv_bfloat16* __restrict__ Al,
    int brow, const float* __restrict__ bias,
    __nv_bfloat16* __restrict__ outH, __nv_bfloat16* __restrict__ outL,
    float* __restrict__ outF,
    int ldc, int colbase, const int* __restrict__ rowmap, int tile0) {
    __nv_bfloat16* sAh = reinterpret_cast<__nv_bfloat16*>(smem_raw);
    __nv_bfloat16* sAl = sAh + kMT * kLds;
    __nv_bfloat16* sBh = sAh + 2 * kMT * kLds;
    __nv_bfloat16* sBl = sBh + 128 * kLds;

    const int tid = threadIdx.x;
    const int wid = tid >> 5, lane = tid & 31;
    const int r  = tid >> 2;
    const int ch = (tid & 3) * 32;

    {
        int n = tid >> 1, bch = (tid & 1) * 64;
        const __nv_bfloat16* srcH = g_Wh + (size_t)(brow + n) * 128 + bch;
        const __nv_bfloat16* srcL = g_Wl + (size_t)(brow + n) * 128 + bch;
        uint32_t dstH = smem_u32(sBh + n * kLds + bch);
        uint32_t dstL = smem_u32(sBl + n * kLds + bch);
#pragma unroll
        for (int q = 0; q < 8; q++) {
            cp_async16(dstH + q * 16, srcH + q * 8);
            cp_async16(dstL + q * 16, srcL + q * 8);
        }
        const __nv_bfloat16* aH = Ah + (size_t)(tile0 * kMT + r) * 128 + ch;
        const __nv_bfloat16* aL = Al + (size_t)(tile0 * kMT + r) * 128 + ch;
        uint32_t adH = smem_u32(sAh + r * kLds + ch);
        uint32_t adL = smem_u32(sAl + r * kLds + ch);
#pragma unroll
        for (int q = 0; q < 4; q++) {
            cp_async16(adH + q * 16, aH + q * 8);
            cp_async16(adL + q * 16, aL + q * 8);
        }
    }
    cp_async_commit_wait();
    __syncthreads();

    const int wm = (wid & 1) * 32;
    const int wn = (wid >> 1) * 32;
    const uint32_t sAh_u = smem_u32(sAh);
    const uint32_t sBh_u = smem_u32(sBh);
    const uint32_t aLo = (uint32_t)(kMT * kLds * 2);
    const uint32_t bLo = (uint32_t)(128 * kLds * 2);

    const int aro = lane & 15;
    const int aco = (lane >> 4) * 8;
    const int bl  = lane & 15;
    const int bro = bl & 7;
    const int bco = ((bl >> 3) & 1) * 8;
    const int g = lane >> 2, tig = lane & 3;

    for (int it = 0; it < TPB; it++) {
        const int m0 = (tile0 + it) * kMT;

        uint4 pf[8];
        if (it + 1 < TPB) {
            const uint4* nH = reinterpret_cast<const uint4*>(
                Ah + (size_t)(m0 + kMT + r) * 128 + ch);
            const uint4* nL = reinterpret_cast<const uint4*>(
                Al + (size_t)(m0 + kMT + r) * 128 + ch);
#pragma unroll
            for (int q = 0; q < 4; q++) { pf[q] = nH[q]; pf[4 + q] = nL[q]; }
        }

        float acc[2][4][4];
#pragma unroll
        for (int mi = 0; mi < 2; mi++)
#pragma unroll
            for (int ni = 0; ni < 4; ni++)
#pragma unroll
                for (int j = 0; j < 4; j++) acc[mi][ni][j] = 0.f;

#pragma unroll
        for (int ks = 0; ks < 8; ks++) {
            uint32_t ah[2][4], al[2][4], bh[4][2], blo[4][2];
#pragma unroll
            for (int mi = 0; mi < 2; mi++) {
                uint32_t addr = sAh_u +
                    (uint32_t)(((wm + mi * 16 + aro) * kLds + ks * 16 + aco) * 2);
                ldsm_x4(ah[mi], addr);
                ldsm_x4(al[mi], addr + aLo);
            }
#pragma unroll
            for (int ni = 0; ni < 4; ni++) {
                uint32_t addr = sBh_u +
                    (uint32_t)(((wn + ni * 8 + bro) * kLds + ks * 16 + bco) * 2);
                ldsm_x2(bh[ni], addr);
                ldsm_x2(blo[ni], addr + bLo);
            }
#pragma unroll
            for (int mi = 0; mi < 2; mi++)
#pragma unroll
                for (int ni = 0; ni < 4; ni++) {
                    mma_bf16(acc[mi][ni], ah[mi], bh[ni]);
                    mma_bf16(acc[mi][ni], ah[mi], blo[ni]);
                    mma_bf16(acc[mi][ni], al[mi], bh[ni]);
                }
        }

#pragma unroll
        for (int mi = 0; mi < 2; mi++) {
            int r0 = m0 + wm + mi * 16 + g;
            int r1 = r0 + 8;
            int or0 = rowmap ? rowmap[r0] : r0;
            int or1 = rowmap ? rowmap[r1] : r1;
#pragma unroll
            for (int ni = 0; ni < 4; ni++) {
                int col = wn + ni * 8 + 2 * tig;
                float b0 = bias[col];
                float b1 = bias[col + 1];
                float v00 = acc[mi][ni][0] + b0, v01 = acc[mi][ni][1] + b1;
                float v10 = acc[mi][ni][2] + b0, v11 = acc[mi][ni][3] + b1;
                if (OUTF32) {
                    *reinterpret_cast<float2*>(outF + (size_t)or0 * ldc + colbase + col) =
                        make_float2(v00, v01);
                    *reinterpret_cast<float2*>(outF + (size_t)or1 * ldc + colbase + col) =
                        make_float2(v10, v11);
                } else {
                    uint32_t h, l;
                    pack_split(v00, v01, h, l);
                    *reinterpret_cast<uint32_t*>(outH + (size_t)or0 * ldc + colbase + col) = h;
                    *reinterpret_cast<uint32_t*>(outL + (size_t)or0 * ldc + colbase + col) = l;
                    pack_split(v10, v11, h, l);
                    *reinterpret_cast<uint32_t*>(outH + (size_t)or1 * ldc + colbase + col) = h;
                    *reinterpret_cast<uint32_t*>(outL + (size_t)or1 * ldc + colbase + col) = l;
                }
            }
        }

        if (it + 1 < TPB) {
            __syncthreads();
            uint4* dH = reinterpret_cast<uint4*>(sAh + r * kLds + ch);
            uint4* dL = reinterpret_cast<uint4*>(sAl + r * kLds + ch);
#pragma unroll
            for (int q = 0; q < 4; q++) { dH[q] = pf[q]; dL[q] = pf[4 + q]; }
            __syncthreads();
        }
    }
}

constexpr int kTPBf = 8;
constexpr int kTPBo = 4;
constexpr int kGrdF = kNTOK / kMT / kTPBf;                // 366
constexpr int kGrdO = kNTOK / kMT / kTPBo;                // 732
static_assert(kNTOK % (kMT * kTPBf) == 0 && kNTOK % (kMT * kTPBo) == 0, "grid");

__global__ __launch_bounds__(256)
void proj_fused() {
    int nt = blockIdx.y;
    const __nv_bfloat16* Ah = (nt == 2) ? g_Fh : g_QKih;
    const __nv_bfloat16* Al = (nt == 2) ? g_Fl : g_QKil;
    if (nt == 2)
        gemm_multi<false, kTPBf>(Ah, Al, 256, g_bias + 256, g_Vph, g_Vpl, nullptr,
                                 128, 0, nullptr, blockIdx.x * kTPBf);
    else
        gemm_multi<false, kTPBf>(Ah, Al, nt * 128, g_bias + nt * 128,
                                 g_QKph, g_QKpl, nullptr, 256, nt * 128, nullptr,
                                 blockIdx.x * kTPBf);
}
__global__ __launch_bounds__(256)
void proj_out(float* __restrict__ out) {
    gemm_multi<true, kTPBo>(g_Oh, g_Ol, 384, g_bias + 384, nullptr, nullptr, out,
                            128, 0, g_s2t, blockIdx.x * kTPBo);
}

// ---------------- MMA attention (R11 math; K planes trimmed to NT*8 rows) --
// MINB: min blocks/SM hint (register budget). K plane rows = NT*8 (<= RowsP).
template <int LV, int WPITCH, int NTHR, int MINB, bool KH, bool VH>
__global__ __launch_bounds__(NTHR, MINB)
void attn_mma(int slotbase, int slotoff) {
    constexpr int MT     = (LV + 15) / 16;
    constexpr int NT     = (LV + 7) / 8;
    constexpr int NTP    = (NT + 1) & ~1;
    constexpr int RowsP  = MT * 16;
    constexpr int KR     = NT * 8;           // K plane rows
    constexpr int Lstr   = 136;
    constexpr int TSZ    = RowsP * Lstr;     // Q/V plane elements
    constexpr int KSZ    = KR * Lstr;        // K plane elements
    constexpr int SLICES = NTHR / 256;
    constexpr int MT0    = (MT + SLICES - 1) / SLICES;
    static_assert(KR >= LV, "K rows cover valid keys");

    __nv_bfloat16* sKh = reinterpret_cast<__nv_bfloat16*>(smem_raw);
    __nv_bfloat16* sKl = sKh + KSZ;
    __nv_bfloat16* sVh = sKh + 2 * KSZ;
    __nv_bfloat16* sVl = sVh + TSZ;
    __nv_bfloat16* sQh = sVh + 2 * TSZ;
    __nv_bfloat16* sQl = sQh + TSZ;

    const int slot0 = slotbase + blockIdx.x * WPITCH + slotoff;
    const int tid = threadIdx.x;

    for (int t = tid; t < RowsP * 16; t += NTHR) {
        int j = t >> 4, c = t & 15;
        uint32_t off = (uint32_t)(j * Lstr * 2 + c * 16);
        if (j < LV) {
            size_t qk = (size_t)(slot0 + j) * 256 + c * 8;
            size_t vv = (size_t)(slot0 + j) * 128 + c * 8;
            cp_async16(smem_u32(sQh) + off, g_QKph + qk);
            cp_async16(smem_u32(sQl) + off, g_QKpl + qk);
            cp_async16(smem_u32(sKh) + off, g_QKph + qk + 128);
            cp_async16(smem_u32(sKl) + off, g_QKpl + qk + 128);
            cp_async16(smem_u32(sVh) + off, g_Vph + vv);
            cp_async16(smem_u32(sVl) + off, g_Vpl + vv);
        } else {
            uint4 z = make_uint4(0u, 0u, 0u, 0u);
            *reinterpret_cast<uint4*>(reinterpret_cast<char*>(sVh) + off) = z;
            *reinterpret_cast<uint4*>(reinterpret_cast<char*>(sVl) + off) = z;
        }
    }
    cp_async_commit_wait();
    __syncthreads();

    const int warp = tid >> 5, lane = tid & 31;
    const int head = warp & 7, slice = warp >> 3;
    const int hb = head * 16;
    const int T = lane >> 2, i4 = lane & 3;
    const int bl = lane & 15;

    const uint32_t uQh = smem_u32(sQh);
    const uint32_t uKh = smem_u32(sKh);
    const uint32_t uVh = smem_u32(sVh);
    const uint32_t LOQ = (uint32_t)(TSZ * 2);
    const uint32_t LOK = (uint32_t)(KSZ * 2);
    const uint32_t LOV = (uint32_t)(TSZ * 2);

    constexpr int KNT = KH ? NT : 1;
    uint32_t khA[KNT][2], klA[KNT][2];
    if (KH) {
#pragma unroll
        for (int nj = 0; nj < NT; nj++) {
            int row = nj * 8 + (bl & 7);
            uint32_t a = uKh + (uint32_t)((row * Lstr + hb + ((bl >> 3) & 1) * 8) * 2);
            ldsm_x2(khA[nj], a);
            ldsm_x2(klA[nj], a + LOK);
        }
    }
    constexpr int KJ = NTP / 2;
    constexpr int VKJ = VH ? KJ : 1;
    uint32_t vhA[VKJ][2], vlA[VKJ][2], vhB[VKJ][2], vlB[VKJ][2];
    if (VH) {
#pragma unroll
        for (int kj = 0; kj < KJ; kj++) {
            uint32_t a0 = uVh + (uint32_t)(((kj * 16 + bl) * Lstr + hb) * 2);
            ldsm_x2_trans(vhA[kj], a0);
            ldsm_x2_trans(vlA[kj], a0 + LOV);
            ldsm_x2_trans(vhB[kj], a0 + 16);
            ldsm_x2_trans(vlB[kj], a0 + 16 + LOV);
        }
    }

    const int miEnd = (slice + 1) * MT0 < MT ? (slice + 1) * MT0 : MT;
#pragma unroll
    for (int mi = slice * MT0; mi < miEnd; mi++) {
        uint32_t qh[4], ql[4];
        {
            int row = mi * 16 + (lane & 15);
            uint32_t a = uQh + (uint32_t)((row * Lstr + hb + (lane >> 4) * 8) * 2);
            ldsm_x4(qh, a);
            ldsm_x4(ql, a + LOQ);
        }

        float s[NTP][4];
        float m0 = -1e30f, m1 = -1e30f;
#pragma unroll
        for (int nj = 0; nj < NT; nj++) {
            uint32_t kh[2], kl[2];
            if (KH) {
                kh[0] = khA[nj][0]; kh[1] = khA[nj][1];
                kl[0] = klA[nj][0]; kl[1] = klA[nj][1];
            } else {
                int row = nj * 8 + (bl & 7);
                uint32_t a = uKh + (uint32_t)((row * Lstr + hb + ((bl >> 3) & 1) * 8) * 2);
                ldsm_x2(kh, a);
                ldsm_x2(kl, a + LOK);
            }
            s[nj][0] = s[nj][1] = s[nj][2] = s[nj][3] = 0.f;
            mma_bf16(s[nj], qh, kh);
            mma_bf16(s[nj], qh, kl);
            mma_bf16(s[nj], ql, kh);
            if (nj * 8 + 7 >= LV) {
                int j0 = nj * 8 + 2 * i4;
                if (j0 >= LV)     { s[nj][0] = -1e30f; s[nj][2] = -1e30f; }
                if (j0 + 1 >= LV) { s[nj][1] = -1e30f; s[nj][3] = -1e30f; }
            }
            m0 = fmaxf(m0, fmaxf(s[nj][0], s[nj][1]));
            m1 = fmaxf(m1, fmaxf(s[nj][2], s[nj][3]));
        }
        m0 = fmaxf(m0, __shfl_xor_sync(0xffffffffu, m0, 1));
        m0 = fmaxf(m0, __shfl_xor_sync(0xffffffffu, m0, 2));
        m1 = fmaxf(m1, __shfl_xor_sync(0xffffffffu, m1, 1));
        m1 = fmaxf(m1, __shfl_xor_sync(0xffffffffu, m1, 2));

        float sum0 = 0.f, sum1 = 0.f;
#pragma unroll
        for (int nj = 0; nj < NT; nj++) {
            s[nj][0] = __expf(s[nj][0] - m0);
            s[nj][1] = __expf(s[nj][1] - m0);
            s[nj][2] = __expf(s[nj][2] - m1);
            s[nj][3] = __expf(s[nj][3] - m1);
            sum0 += s[nj][0] + s[nj][1];
            sum1 += s[nj][2] + s[nj][3];
        }
#pragma unroll
        for (int nj = NT; nj < NTP; nj++)
            s[nj][0] = s[nj][1] = s[nj][2] = s[nj][3] = 0.f;
        sum0 += __shfl_xor_sync(0xffffffffu, sum0, 1);
        sum0 += __shfl_xor_sync(0xffffffffu, sum0, 2);
        sum1 += __shfl_xor_sync(0xffffffffu, sum1, 1);
        sum1 += __shfl_xor_sync(0xffffffffu, sum1, 2);

        float o0[4] = {0.f, 0.f, 0.f, 0.f};
        float o1[4] = {0.f, 0.f, 0.f, 0.f};
#pragma unroll
        for (int kj = 0; kj < KJ; kj++) {
            uint32_t ah[4], al[4];
            pack_split(s[2 * kj][0],     s[2 * kj][1],     ah[0], al[0]);
            pack_split(s[2 * kj][2],     s[2 * kj][3],     ah[1], al[1]);
            pack_split(s[2 * kj + 1][0], s[2 * kj + 1][1], ah[2], al[2]);
            pack_split(s[2 * kj + 1][2], s[2 * kj + 1][3], ah[3], al[3]);
            uint32_t vh0[2], vl0[2], vh1[2], vl1[2];
            if (VH) {
                vh0[0] = vhA[kj][0]; vh0[1] = vhA[kj][1];
                vl0[0] = vlA[kj][0]; vl0[1] = vlA[kj][1];
                vh1[0] = vhB[kj][0]; vh1[1] = vhB[kj][1];
                vl1[0] = vlB[kj][0]; vl1[1] = vlB[kj][1];
            } else {
                uint32_t a0 = uVh + (uint32_t)(((kj * 16 + bl) * Lstr + hb) * 2);
                ldsm_x2_trans(vh0, a0);
                ldsm_x2_trans(vl0, a0 + LOV);
                ldsm_x2_trans(vh1, a0 + 16);
                ldsm_x2_trans(vl1, a0 + 16 + LOV);
            }
            mma_bf16(o0, ah, vh0);
            mma_bf16(o0, ah, vl0);
            mma_bf16(o0, al, vh0);
            mma_bf16(o1, ah, vh1);
            mma_bf16(o1, ah, vl1);
            mma_bf16(o1, al, vh1);
        }

        float inv0 = 1.f / sum0, inv1 = 1.f / sum1;
        int r0 = mi * 16 + T, r1 = r0 + 8;
        int col = hb + 2 * i4;
        if (r0 < LV) {
            size_t base = (size_t)(slot0 + r0) * 128 + col;
            uint32_t h, l;
            pack_split(o0[0] * inv0, o0[1] * inv0, h, l);
            *reinterpret_cast<uint32_t*>(g_Oh + base) = h;
            *reinterpret_cast<uint32_t*>(g_Ol + base) = l;
            pack_split(o1[0] * inv0, o1[1] * inv0, h, l);
            *reinterpret_cast<uint32_t*>(g_Oh + base + 8) = h;
            *reinterpret_cast<uint32_t*>(g_Ol + base + 8) = l;
        }
        if (r1 < LV) {
            size_t base = (size_t)(slot0 + r1) * 128 + col;
            uint32_t h, l;
            pack_split(o0[2] * inv1, o0[3] * inv1, h, l);
            *reinterpret_cast<uint32_t*>(g_Oh + base) = h;
            *reinterpret_cast<uint32_t*>(g_Ol + base) = l;
            pack_split(o1[2] * inv1, o1[3] * inv1, h, l);
            *reinterpret_cast<uint32_t*>(g_Oh + base + 8) = h;
            *reinterpret_cast<uint32_t*>(g_Ol + base + 8) = l;
        }
    }
}

// ---------------- launch ----------------
template <int LV>
constexpr int attn_smem() {
    constexpr int RowsP = ((LV + 15) / 16) * 16;
    constexpr int KR    = ((LV + 7) / 8) * 8;
    return (2 * KR + 4 * RowsP) * 136 * 2;
}

extern "C" void kernel_launch(void* const* d_in, const int* in_sizes, int n_in,
                              void* d_out, int out_size) {
    const float* feat  = (const float*)d_in[0];
    const float* pos1  = (const float*)d_in[1];
    const float* pos2  = (const float*)d_in[2];
    const float* Wi    = (const float*)d_in[3];
    const float* bi    = (const float*)d_in[4];
    const float* Wo    = (const float*)d_in[5];
    const float* bo    = (const float*)d_in[6];
    const int*   inds1 = (const int*)d_in[7];
    const int*   inds2 = (const int*)d_in[8];
    float* out = (float*)d_out;

    cudaFuncSetAttribute(proj_fused, cudaFuncAttributeMaxDynamicSharedMemorySize, kTcSmem);
    cudaFuncSetAttribute(proj_out,   cudaFuncAttributeMaxDynamicSharedMemorySize, kTcSmem);
    cudaFuncSetAttribute((const void*)attn_mma<kL1, 54, 256, 3, true, false>,
                         cudaFuncAttributeMaxDynamicSharedMemorySize, attn_smem<kL1>());
    cudaFuncSetAttribute((const void*)attn_mma<kL1 / 2, 54, 256, 3, true, true>,
                         cudaFuncAttributeMaxDynamicSharedMemorySize, attn_smem<kL1 / 2>());
    cudaFuncSetAttribute((const void*)attn_mma<kL2, 150, 512, 1, false, false>,
                         cudaFuncAttributeMaxDynamicSharedMemorySize, attn_smem<kL2>());
    cudaFuncSetAttribute((const void*)attn_mma<kL2 / 2, 150, 256, 2, true, false>,
                         cudaFuncAttributeMaxDynamicSharedMemorySize, attn_smem<kL2 / 2>());

    // 1) fused: gather split(feat+pos)/split(feat) + weight/bias prep + s2t
    gather_prep_kernel<<<kNWALL + kPrepBlocks, 256>>>(
        feat, pos1, pos2, inds1, inds2, Wi, Wo, bi, bo);
    // 2) fused Q/K/V projections (B resident, 8 M-tiles/block, reg prefetch)
    proj_fused<<<dim3(kGrdF, 3), 256, kTcSmem>>>();
    // 3) windowed attention (K planes trimmed; <36> now 3 blocks/SM)
    attn_mma<kL1, 54, 256, 3, true, false><<<kNW1 / 2, 256, attn_smem<kL1>()>>>(0, 0);
    attn_mma<kL1 / 2, 54, 256, 3, true, true><<<kNW1 / 2, 256, attn_smem<kL1 / 2>()>>>(0, kL1);
    attn_mma<kL2, 150, 512, 1, false, false><<<kNW2 / 2, 512, attn_smem<kL2>()>>>(kN1, 0);
    attn_mma<kL2 / 2, 150, 256, 2, true, false><<<kNW2 / 2, 256, attn_smem<kL2 / 2>()>>>(kN1, kL2);
    // 4) output projection with row scatter (bijective -> no init/atomics)
    proj_out<<<kGrdO, 256, kTcSmem>>>(out);
}

// round 16
// speedup vs baseline: 1.4130x; 1.4130x over previous
#include <cuda_runtime.h>
#include <cuda_bf16.h>
#include <cstdint>

// ---------------- problem constants ----------------
constexpr int kD     = 128;
constexpr int kNH    = 8;
constexpr int kHD    = 16;
constexpr int kNW1   = 4096;
constexpr int kL1    = 36;
constexpr int kNW2   = 1024;
constexpr int kL2    = 100;
constexpr int kN1    = (kNW1 / 2) * (kL1 + kL1 / 2);   // 110592
constexpr int kN2    = (kNW2 / 2) * (kL2 + kL2 / 2);   // 76800
constexpr int kNTOK  = kN1 + kN2;                      // 187392 == 1464*128

static_assert(kNTOK % 128 == 0, "M tile");

extern __shared__ char smem_raw[];

// ---------------- device scratch (all inter-stage data pre-split bf16) -----
__device__ __nv_bfloat16 g_QKih[(size_t)kNTOK * 128];
__device__ __nv_bfloat16 g_QKil[(size_t)kNTOK * 128];
__device__ __nv_bfloat16 g_Fh  [(size_t)kNTOK * 128];   // feat, slot order
__device__ __nv_bfloat16 g_Fl  [(size_t)kNTOK * 128];
__device__ __nv_bfloat16 g_QKph[(size_t)kNTOK * 256];
__device__ __nv_bfloat16 g_QKpl[(size_t)kNTOK * 256];
__device__ __nv_bfloat16 g_Vph [(size_t)kNTOK * 128];
__device__ __nv_bfloat16 g_Vpl [(size_t)kNTOK * 128];
__device__ __nv_bfloat16 g_Oh  [(size_t)kNTOK * 128];
__device__ __nv_bfloat16 g_Ol  [(size_t)kNTOK * 128];
__device__ int   g_s2t [kNTOK];
__device__ float g_bias[512];
__device__ __nv_bfloat16 g_Wh[512 * 128];
__device__ __nv_bfloat16 g_Wl[512 * 128];

// ---------------- PTX helpers (sm_80+ generic) ----------------
__device__ __forceinline__ uint32_t smem_u32(const void* p) {
    uint32_t a;
    asm("{ .reg .u64 t; cvta.to.shared.u64 t, %1; cvt.u32.u64 %0, t; }"
        : "=r"(a) : "l"(p));
    return a;
}
__device__ __forceinline__ void cp_async16(uint32_t dst, const void* src) {
    asm volatile("cp.async.cg.shared.global [%0], [%1], 16;"
                 :: "r"(dst), "l"(src) : "memory");
}
__device__ __forceinline__ void cp_async_commit_wait() {
    asm volatile("cp.async.commit_group;" ::: "memory");
    asm volatile("cp.async.wait_group 0;" ::: "memory");
}
__device__ __forceinline__ void ldsm_x4(uint32_t* r, uint32_t a) {
    asm volatile("ldmatrix.sync.aligned.m8n8.x4.shared.b16 {%0,%1,%2,%3}, [%4];"
                 : "=r"(r[0]), "=r"(r[1]), "=r"(r[2]), "=r"(r[3]) : "r"(a));
}
__device__ __forceinline__ void ldsm_x2(uint32_t* r, uint32_t a) {
    asm volatile("ldmatrix.sync.aligned.m8n8.x2.shared.b16 {%0,%1}, [%2];"
                 : "=r"(r[0]), "=r"(r[1]) : "r"(a));
}
__device__ __forceinline__ void ldsm_x2_trans(uint32_t* r, uint32_t a) {
    asm volatile("ldmatrix.sync.aligned.m8n8.x2.trans.shared.b16 {%0,%1}, [%2];"
                 : "=r"(r[0]), "=r"(r[1]) : "r"(a));
}
__device__ __forceinline__ void mma_bf16(float* d, const uint32_t* a, const uint32_t* b) {
    asm volatile(
        "mma.sync.aligned.m16n8k16.row.col.f32.bf16.bf16.f32 "
        "{%0,%1,%2,%3}, {%4,%5,%6,%7}, {%8,%9}, {%0,%1,%2,%3};"
        : "+f"(d[0]), "+f"(d[1]), "+f"(d[2]), "+f"(d[3])
        : "r"(a[0]), "r"(a[1]), "r"(a[2]), "r"(a[3]), "r"(b[0]), "r"(b[1]));
}
__device__ __forceinline__ void pack_split(float x, float y, uint32_t& h, uint32_t& l) {
    __nv_bfloat162 hh = __floats2bfloat162_rn(x, y);
    __nv_bfloat162 ll = __floats2bfloat162_rn(x - __bfloat162float(hh.x),
                                              y - __bfloat162float(hh.y));
    h = *reinterpret_cast<uint32_t*>(&hh);
    l = *reinterpret_cast<uint32_t*>(&ll);
}
__device__ __forceinline__ void split_store(__nv_bfloat16* hi, __nv_bfloat16* lo,
                                            size_t idx, float4 v) {
    uint32_t h0, l0, h1, l1;
    pack_split(v.x, v.y, h0, l0);
    pack_split(v.z, v.w, h1, l1);
    *reinterpret_cast<uint2*>(hi + idx) = make_uint2(h0, h1);
    *reinterpret_cast<uint2*>(lo + idx) = make_uint2(l0, l1);
}

// ---------------- fused prep: gather planes + weight split + maps ---------
constexpr int kNWALL = kNW1 + kNW2;                 // 5120
constexpr int kPrepBlocks = (512 * 128) / 256;      // 256

__global__ __launch_bounds__(256)
void gather_prep_kernel(const float* __restrict__ feat,
                        const float* __restrict__ pos1,
                        const float* __restrict__ pos2,
                        const int* __restrict__ inds1,
                        const int* __restrict__ inds2,
                        const float* __restrict__ Wi,
                        const float* __restrict__ Wo,
                        const float* __restrict__ bi,
                        const float* __restrict__ bo) {
    int w = blockIdx.x;
    if (w >= kNWALL) {
        int t = (w - kNWALL) * 256 + threadIdx.x;
        if (w == kNWALL && threadIdx.x < 256) {
            for (int b = threadIdx.x; b < 512; b += 256) {
                float v = (b < 128) ? bi[b] * 0.25f
                                    : (b < 384 ? bi[b] : bo[b - 384]);
                g_bias[b] = v;
            }
        }
        if (t < 512 * 128) {
            float wv = (t < 384 * 128) ? Wi[t] : Wo[t - 384 * 128];
            if (t < 128 * 128) wv *= 0.25f;   // fold score scale into Q
            __nv_bfloat16 h = __float2bfloat16(wv);
            __nv_bfloat16 l = __float2bfloat16(wv - __bfloat162float(h));
            g_Wh[t] = h;
            g_Wl[t] = l;
        }
        return;
    }
    int Lv, slot0;
    const int* inds;
    const float* pos;
    if (w < kNW1) {
        Lv    = (w & 1) ? (kL1 / 2) : kL1;
        slot0 = (w >> 1) * (kL1 + kL1 / 2) + (w & 1) * kL1;
        inds  = inds1 + w * kL1;
        pos   = pos1 + (size_t)w * kL1 * 128;
    } else {
        int w2 = w - kNW1;
        Lv    = (w2 & 1) ? (kL2 / 2) : kL2;
        slot0 = kN1 + (w2 >> 1) * (kL2 + kL2 / 2) + (w2 & 1) * kL2;
        inds  = inds2 + w2 * kL2;
        pos   = pos2 + (size_t)w2 * kL2 * 128;
    }
    for (int t = threadIdx.x; t < Lv * 32; t += 256) {
        int l = t >> 5, c = t & 31;
        int tok = inds[l];
        float4 f = reinterpret_cast<const float4*>(feat + (size_t)tok * 128)[c];
        float4 p = reinterpret_cast<const float4*>(pos + (size_t)l * 128)[c];
        float4 r;
        r.x = f.x + p.x; r.y = f.y + p.y; r.z = f.z + p.z; r.w = f.w + p.w;
        size_t idx = (size_t)(slot0 + l) * 128 + c * 4;
        split_store(g_QKih, g_QKil, idx, r);
        split_store(g_Fh, g_Fl, idx, f);
        if (c == 0) g_s2t[slot0 + l] = tok;
    }
}

// ---------------- multi-tile HMMA GEMM, B resident, A reg-prefetch --------
constexpr int kLds  = 136;
constexpr int kMT   = 64;
constexpr int kTcSmem = (2 * kMT + 2 * 128) * kLds * 2;   // 104448 B

template <bool OUTF32, int TPB>
__device__ __forceinline__ void gemm_multi(
    const __nv_bfloat16* __restrict__ Ah, const __nv_bfloat16* __restrict__ Al,
    int brow, const float* __restrict__ bias,
    __nv_bfloat16* __restrict__ outH, __nv_bfloat16* __restrict__ outL,
    float* __restrict__ outF,
    int ldc, int colbase, const int* __restrict__ rowmap, int tile0) {
    __nv_bfloat16* sAh = reinterpret_cast<__nv_bfloat16*>(smem_raw);
    __nv_bfloat16* sAl = sAh + kMT * kLds;
    __nv_bfloat16* sBh = sAh + 2 * kMT * kLds;
    __nv_bfloat16* sBl = sBh + 128 * kLds;

    const int tid = threadIdx.x;
    const int wid = tid >> 5, lane = tid & 31;
    const int r  = tid >> 2;
    const int ch = (tid & 3) * 32;

    {
        int n = tid >> 1, bch = (tid & 1) * 64;
        const __nv_bfloat16* srcH = g_Wh + (size_t)(brow + n) * 128 + bch;
        const __nv_bfloat16* srcL = g_Wl + (size_t)(brow + n) * 128 + bch;
        uint32_t dstH = smem_u32(sBh + n * kLds + bch);
        uint32_t dstL = smem_u32(sBl + n * kLds + bch);
#pragma unroll
        for (int q = 0; q < 8; q++) {
            cp_async16(dstH + q * 16, srcH + q * 8);
            cp_async16(dstL + q * 16, srcL + q * 8);
        }
        const __nv_bfloat16* aH = Ah + (size_t)(tile0 * kMT + r) * 128 + ch;
        const __nv_bfloat16* aL = Al + (size_t)(tile0 * kMT + r) * 128 + ch;
        uint32_t adH = smem_u32(sAh + r * kLds + ch);
        uint32_t adL = smem_u32(sAl + r * kLds + ch);
#pragma unroll
        for (int q = 0; q < 4; q++) {
            cp_async16(adH + q * 16, aH + q * 8);
            cp_async16(adL + q * 16, aL + q * 8);
        }
    }
    cp_async_commit_wait();
    __syncthreads();

    const int wm = (wid & 1) * 32;
    const int wn = (wid >> 1) * 32;
    const uint32_t sAh_u = smem_u32(sAh);
    const uint32_t sBh_u = smem_u32(sBh);
    const uint32_t aLo = (uint32_t)(kMT * kLds * 2);
    const uint32_t bLo = (uint32_t)(128 * kLds * 2);

    const int aro = lane & 15;
    const int aco = (lane >> 4) * 8;
    const int bl  = lane & 15;
    const int bro = bl & 7;
    const int bco = ((bl >> 3) & 1) * 8;
    const int g = lane >> 2, tig = lane & 3;

    for (int it = 0; it < TPB; it++) {
        const int m0 = (tile0 + it) * kMT;

        uint4 pf[8];
        if (it + 1 < TPB) {
            const uint4* nH = reinterpret_cast<const uint4*>(
                Ah + (size_t)(m0 + kMT + r) * 128 + ch);
            const uint4* nL = reinterpret_cast<const uint4*>(
                Al + (size_t)(m0 + kMT + r) * 128 + ch);
#pragma unroll
            for (int q = 0; q < 4; q++) { pf[q] = nH[q]; pf[4 + q] = nL[q]; }
        }

        float acc[2][4][4];
#pragma unroll
        for (int mi = 0; mi < 2; mi++)
#pragma unroll
            for (int ni = 0; ni < 4; ni++)
#pragma unroll
                for (int j = 0; j < 4; j++) acc[mi][ni][j] = 0.f;

#pragma unroll
        for (int ks = 0; ks < 8; ks++) {
            uint32_t ah[2][4], al[2][4], bh[4][2], blo[4][2];
#pragma unroll
            for (int mi = 0; mi < 2; mi++) {
                uint32_t addr = sAh_u +
                    (uint32_t)(((wm + mi * 16 + aro) * kLds + ks * 16 + aco) * 2);
                ldsm_x4(ah[mi], addr);
                ldsm_x4(al[mi], addr + aLo);
            }
#pragma unroll
            for (int ni = 0; ni < 4; ni++) {
                uint32_t addr = sBh_u +
                    (uint32_t)(((wn + ni * 8 + bro) * kLds + ks * 16 + bco) * 2);
                ldsm_x2(bh[ni], addr);
                ldsm_x2(blo[ni], addr + bLo);
            }
#pragma unroll
            for (int mi = 0; mi < 2; mi++)
#pragma unroll
                for (int ni = 0; ni < 4; ni++) {
                    mma_bf16(acc[mi][ni], ah[mi], bh[ni]);
                    mma_bf16(acc[mi][ni], ah[mi], blo[ni]);
                    mma_bf16(acc[mi][ni], al[mi], bh[ni]);
                }
        }

#pragma unroll
        for (int mi = 0; mi < 2; mi++) {
            int r0 = m0 + wm + mi * 16 + g;
            int r1 = r0 + 8;
            int or0 = rowmap ? rowmap[r0] : r0;
            int or1 = rowmap ? rowmap[r1] : r1;
#pragma unroll
            for (int ni = 0; ni < 4; ni++) {
                int col = wn + ni * 8 + 2 * tig;
                float b0 = bias[col];
                float b1 = bias[col + 1];
                float v00 = acc[mi][ni][0] + b0, v01 = acc[mi][ni][1] + b1;
                float v10 = acc[mi][ni][2] + b0, v11 = acc[mi][ni][3] + b1;
                if (OUTF32) {
                    *reinterpret_cast<float2*>(outF + (size_t)or0 * ldc + colbase + col) =
                        make_float2(v00, v01);
                    *reinterpret_cast<float2*>(outF + (size_t)or1 * ldc + colbase + col) =
                        make_float2(v10, v11);
                } else {
                    uint32_t h, l;
                    pack_split(v00, v01, h, l);
                    *reinterpret_cast<uint32_t*>(outH + (size_t)or0 * ldc + colbase + col) = h;
                    *reinterpret_cast<uint32_t*>(outL + (size_t)or0 * ldc + colbase + col) = l;
                    pack_split(v10, v11, h, l);
                    *reinterpret_cast<uint32_t*>(outH + (size_t)or1 * ldc + colbase + col) = h;
                    *reinterpret_cast<uint32_t*>(outL + (size_t)or1 * ldc + colbase + col) = l;
                }
            }
        }

        if (it + 1 < TPB) {
            __syncthreads();
            uint4* dH = reinterpret_cast<uint4*>(sAh + r * kLds + ch);
            uint4* dL = reinterpret_cast<uint4*>(sAl + r * kLds + ch);
#pragma unroll
            for (int q = 0; q < 4; q++) { dH[q] = pf[q]; dL[q] = pf[4 + q]; }
            __syncthreads();
        }
    }
}

constexpr int kTPBf = 8;
constexpr int kTPBo = 4;
constexpr int kGrdF = kNTOK / kMT / kTPBf;                // 366
constexpr int kGrdO = kNTOK / kMT / kTPBo;                // 732
static_assert(kNTOK % (kMT * kTPBf) == 0 && kNTOK % (kMT * kTPBo) == 0, "grid");

__global__ __launch_bounds__(256)
void proj_fused() {
    int nt = blockIdx.y;
    const __nv_bfloat16* Ah = (nt == 2) ? g_Fh : g_QKih;
    const __nv_bfloat16* Al = (nt == 2) ? g_Fl : g_QKil;
    if (nt == 2)
        gemm_multi<false, kTPBf>(Ah, Al, 256, g_bias + 256, g_Vph, g_Vpl, nullptr,
                                 128, 0, nullptr, blockIdx.x * kTPBf);
    else
        gemm_multi<false, kTPBf>(Ah, Al, nt * 128, g_bias + nt * 128,
                                 g_QKph, g_QKpl, nullptr, 256, nt * 128, nullptr,
                                 blockIdx.x * kTPBf);
}
__global__ __launch_bounds__(256)
void proj_out(float* __restrict__ out) {
    gemm_multi<true, kTPBo>(g_Oh, g_Ol, 384, g_bias + 384, nullptr, nullptr, out,
                            128, 0, g_s2t, blockIdx.x * kTPBo);
}

// ---------------- MMA attention (verified R11 variants) ----------------
template <int LV, int WPITCH, int NTHR, bool KH, bool VH>
__global__ __launch_bounds__(NTHR)
void attn_mma(int slotbase, int slotoff) {
    constexpr int MT     = (LV + 15) / 16;
    constexpr int NT     = (LV + 7) / 8;
    constexpr int NTP    = (NT + 1) & ~1;
    constexpr int RowsP  = MT * 16;
    constexpr int Lstr   = 136;
    constexpr int TSZ    = RowsP * Lstr;
    constexpr int SLICES = NTHR / 256;
    constexpr int MT0    = (MT + SLICES - 1) / SLICES;
    static_assert(NTP * 8 <= RowsP, "key pad fits");

    __nv_bfloat16* sQh = reinterpret_cast<__nv_bfloat16*>(smem_raw);
    __nv_bfloat16* sQl = sQh + TSZ;
    __nv_bfloat16* sKh = sQh + 2 * TSZ;
    __nv_bfloat16* sKl = sQh + 3 * TSZ;
    __nv_bfloat16* sVh = sQh + 4 * TSZ;
    __nv_bfloat16* sVl = sQh + 5 * TSZ;

    const int slot0 = slotbase + blockIdx.x * WPITCH + slotoff;
    const int tid = threadIdx.x;

    for (int t = tid; t < RowsP * 16; t += NTHR) {
        int j = t >> 4, c = t & 15;
        uint32_t off = (uint32_t)(j * Lstr * 2 + c * 16);
        if (j < LV) {
            size_t qk = (size_t)(slot0 + j) * 256 + c * 8;
            size_t vv = (size_t)(slot0 + j) * 128 + c * 8;
            cp_async16(smem_u32(sQh) + off, g_QKph + qk);
            cp_async16(smem_u32(sQl) + off, g_QKpl + qk);
            cp_async16(smem_u32(sKh) + off, g_QKph + qk + 128);
            cp_async16(smem_u32(sKl) + off, g_QKpl + qk + 128);
            cp_async16(smem_u32(sVh) + off, g_Vph + vv);
            cp_async16(smem_u32(sVl) + off, g_Vpl + vv);
        } else {
            uint4 z = make_uint4(0u, 0u, 0u, 0u);
            *reinterpret_cast<uint4*>(reinterpret_cast<char*>(sVh) + off) = z;
            *reinterpret_cast<uint4*>(reinterpret_cast<char*>(sVl) + off) = z;
        }
    }
    cp_async_commit_wait();
    __syncthreads();

    const int warp = tid >> 5, lane = tid & 31;
    const int head = warp & 7, slice = warp >> 3;
    const int hb = head * 16;
    const int T = lane >> 2, i4 = lane & 3;
    const int bl = lane & 15;

    const uint32_t uQh = smem_u32(sQh);
    const uint32_t uKh = smem_u32(sKh);
    const uint32_t uVh = smem_u32(sVh);
    const uint32_t LO  = (uint32_t)(TSZ * 2);

    constexpr int KNT = KH ? NT : 1;
    uint32_t khA[KNT][2], klA[KNT][2];
    if (KH) {
#pragma unroll
        for (int nj = 0; nj < NT; nj++) {
            int row = nj * 8 + (bl & 7);
            uint32_t a = uKh + (uint32_t)((row * Lstr + hb + ((bl >> 3) & 1) * 8) * 2);
            ldsm_x2(khA[nj], a);
            ldsm_x2(klA[nj], a + LO);
        }
    }
    constexpr int KJ = NTP / 2;
    constexpr int VKJ = VH ? KJ : 1;
    uint32_t vhA[VKJ][2], vlA[VKJ][2], vhB[VKJ][2], vlB[VKJ][2];
    if (VH) {
#pragma unroll
        for (int kj = 0; kj < KJ; kj++) {
            uint32_t a0 = uVh + (uint32_t)(((kj * 16 + bl) * Lstr + hb) * 2);
            ldsm_x2_trans(vhA[kj], a0);
            ldsm_x2_trans(vlA[kj], a0 + LO);
            ldsm_x2_trans(vhB[kj], a0 + 16);
            ldsm_x2_trans(vlB[kj], a0 + 16 + LO);
        }
    }

    const int miEnd = (slice + 1) * MT0 < MT ? (slice + 1) * MT0 : MT;
#pragma unroll
    for (int mi = slice * MT0; mi < miEnd; mi++) {
        uint32_t qh[4], ql[4];
        {
            int row = mi * 16 + (lane & 15);
            uint32_t a = uQh + (uint32_t)((row * Lstr + hb + (lane >> 4) * 8) * 2);
            ldsm_x4(qh, a);
            ldsm_x4(ql, a + LO);
        }

        float s[NTP][4];
        float m0 = -1e30f, m1 = -1e30f;
#pragma unroll
        for (int nj = 0; nj < NT; nj++) {
            uint32_t kh[2], kl[2];
            if (KH) {
                kh[0] = khA[nj][0]; kh[1] = khA[nj][1];
                kl[0] = klA[nj][0]; kl[1] = klA[nj][1];
            } else {
                int row = nj * 8 + (bl & 7);
                uint32_t a = uKh + (uint32_t)((row * Lstr + hb + ((bl >> 3) & 1) * 8) * 2);
                ldsm_x2(kh, a);
                ldsm_x2(kl, a + LO);
            }
            s[nj][0] = s[nj][1] = s[nj][2] = s[nj][3] = 0.f;
            mma_bf16(s[nj], qh, kh);
            mma_bf16(s[nj], qh, kl);
            mma_bf16(s[nj], ql, kh);
            if (nj * 8 + 7 >= LV) {
                int j0 = nj * 8 + 2 * i4;
                if (j0 >= LV)     { s[nj][0] = -1e30f; s[nj][2] = -1e30f; }
                if (j0 + 1 >= LV) { s[nj][1] = -1e30f; s[nj][3] = -1e30f; }
            }
            m0 = fmaxf(m0, fmaxf(s[nj][0], s[nj][1]));
            m1 = fmaxf(m1, fmaxf(s[nj][2], s[nj][3]));
        }
        m0 = fmaxf(m0, __shfl_xor_sync(0xffffffffu, m0, 1));
        m0 = fmaxf(m0, __shfl_xor_sync(0xffffffffu, m0, 2));
        m1 = fmaxf(m1, __shfl_xor_sync(0xffffffffu, m1, 1));
        m1 = fmaxf(m1, __shfl_xor_sync(0xffffffffu, m1, 2));

        float sum0 = 0.f, sum1 = 0.f;
#pragma unroll
        for (int nj = 0; nj < NT; nj++) {
            s[nj][0] = __expf(s[nj][0] - m0);
            s[nj][1] = __expf(s[nj][1] - m0);
            s[nj][2] = __expf(s[nj][2] - m1);
            s[nj][3] = __expf(s[nj][3] - m1);
            sum0 += s[nj][0] + s[nj][1];
            sum1 += s[nj][2] + s[nj][3];
        }
#pragma unroll
        for (int nj = NT; nj < NTP; nj++)
            s[nj][0] = s[nj][1] = s[nj][2] = s[nj][3] = 0.f;
        sum0 += __shfl_xor_sync(0xffffffffu, sum0, 1);
        sum0 += __shfl_xor_sync(0xffffffffu, sum0, 2);
        sum1 += __shfl_xor_sync(0xffffffffu, sum1, 1);
        sum1 += __shfl_xor_sync(0xffffffffu, sum1, 2);

        float o0[4] = {0.f, 0.f, 0.f, 0.f};
        float o1[4] = {0.f, 0.f, 0.f, 0.f};
#pragma unroll
        for (int kj = 0; kj < KJ; kj++) {
            uint32_t ah[4], al[4];
            pack_split(s[2 * kj][0],     s[2 * kj][1],     ah[0], al[0]);
            pack_split(s[2 * kj][2],     s[2 * kj][3],     ah[1], al[1]);
            pack_split(s[2 * kj + 1][0], s[2 * kj + 1][1], ah[2], al[2]);
            pack_split(s[2 * kj + 1][2], s[2 * kj + 1][3], ah[3], al[3]);
            uint32_t vh0[2], vl0[2], vh1[2], vl1[2];
            if (VH) {
                vh0[0] = vhA[kj][0]; vh0[1] = vhA[kj][1];
                vl0[0] = vlA[kj][0]; vl0[1] = vlA[kj][1];
                vh1[0] = vhB[kj][0]; vh1[1] = vhB[kj][1];
                vl1[0] = vlB[kj][0]; vl1[1] = vlB[kj][1];
            } else {
                uint32_t a0 = uVh + (uint32_t)(((kj * 16 + bl) * Lstr + hb) * 2);
                ldsm_x2_trans(vh0, a0);
                ldsm_x2_trans(vl0, a0 + LO);
                ldsm_x2_trans(vh1, a0 + 16);
                ldsm_x2_trans(vl1, a0 + 16 + LO);
            }
            mma_bf16(o0, ah, vh0);
            mma_bf16(o0, ah, vl0);
            mma_bf16(o0, al, vh0);
            mma_bf16(o1, ah, vh1);
            mma_bf16(o1, ah, vl1);
            mma_bf16(o1, al, vh1);
        }

        float inv0 = 1.f / sum0, inv1 = 1.f / sum1;
        int r0 = mi * 16 + T, r1 = r0 + 8;
        int col = hb + 2 * i4;
        if (r0 < LV) {
            size_t base = (size_t)(slot0 + r0) * 128 + col;
            uint32_t h, l;
            pack_split(o0[0] * inv0, o0[1] * inv0, h, l);
            *reinterpret_cast<uint32_t*>(g_Oh + base) = h;
            *reinterpret_cast<uint32_t*>(g_Ol + base) = l;
            pack_split(o1[0] * inv0, o1[1] * inv0, h, l);
            *reinterpret_cast<uint32_t*>(g_Oh + base + 8) = h;
            *reinterpret_cast<uint32_t*>(g_Ol + base + 8) = l;
        }
        if (r1 < LV) {
            size_t base = (size_t)(slot0 + r1) * 128 + col;
            uint32_t h, l;
            pack_split(o0[2] * inv1, o0[3] * inv1, h, l);
            *reinterpret_cast<uint32_t*>(g_Oh + base) = h;
            *reinterpret_cast<uint32_t*>(g_Ol + base) = l;
            pack_split(o1[2] * inv1, o1[3] * inv1, h, l);
            *reinterpret_cast<uint32_t*>(g_Oh + base + 8) = h;
            *reinterpret_cast<uint32_t*>(g_Ol + base + 8) = l;
        }
    }
}

// ---------------- launch ----------------
template <int LV>
constexpr int attn_smem() { return 6 * (((LV + 15) / 16) * 16) * 136 * 2; }

extern "C" void kernel_launch(void* const* d_in, const int* in_sizes, int n_in,
                              void* d_out, int out_size) {
    const float* feat  = (const float*)d_in[0];
    const float* pos1  = (const float*)d_in[1];
    const float* pos2  = (const float*)d_in[2];
    const float* Wi    = (const float*)d_in[3];
    const float* bi    = (const float*)d_in[4];
    const float* Wo    = (const float*)d_in[5];
    const float* bo    = (const float*)d_in[6];
    const int*   inds1 = (const int*)d_in[7];
    const int*   inds2 = (const int*)d_in[8];
    float* out = (float*)d_out;

    cudaFuncSetAttribute(proj_fused, cudaFuncAttributeMaxDynamicSharedMemorySize, kTcSmem);
    cudaFuncSetAttribute(proj_out,   cudaFuncAttributeMaxDynamicSharedMemorySize, kTcSmem);
    cudaFuncSetAttribute((const void*)attn_mma<kL1, 54, 256, true, true>,
                         cudaFuncAttributeMaxDynamicSharedMemorySize, attn_smem<kL1>());
    cudaFuncSetAttribute((const void*)attn_mma<kL1 / 2, 54, 256, true, true>,
                         cudaFuncAttributeMaxDynamicSharedMemorySize, attn_smem<kL1 / 2>());
    cudaFuncSetAttribute((const void*)attn_mma<kL2, 150, 512, false, false>,
                         cudaFuncAttributeMaxDynamicSharedMemorySize, attn_smem<kL2>());
    cudaFuncSetAttribute((const void*)attn_mma<kL2 / 2, 150, 256, true, false>,
                         cudaFuncAttributeMaxDynamicSharedMemorySize, attn_smem<kL2 / 2>());

    // 1) fused: gather split(feat+pos)/split(feat) + weight/bias prep + s2t
    gather_prep_kernel<<<kNWALL + kPrepBlocks, 256>>>(
        feat, pos1, pos2, inds1, inds2, Wi, Wo, bi, bo);
    // 2) fused Q/K/V projections (B resident, 8 M-tiles/block, reg prefetch)
    proj_fused<<<dim3(kGrdF, 3), 256, kTcSmem>>>();
    // 3) windowed attention
    attn_mma<kL1, 54, 256, true, true><<<kNW1 / 2, 256, attn_smem<kL1>()>>>(0, 0);
    attn_mma<kL1 / 2, 54, 256, true, true><<<kNW1 / 2, 256, attn_smem<kL1 / 2>()>>>(0, kL1);
    attn_mma<kL2, 150, 512, false, false><<<kNW2 / 2, 512, attn_smem<kL2>()>>>(kN1, 0);
    attn_mma<kL2 / 2, 150, 256, true, false><<<kNW2 / 2, 256, attn_smem<kL2 / 2>()>>>(kN1, kL2);
    // 4) output projection with row scatter (bijective -> no init/atomics)
    proj_out<<<kGrdO, 256, kTcSmem>>>(out);
}